// round 3
// baseline (speedup 1.0000x reference)
#include <cuda_runtime.h>

// RamanAmplifier on GB300 — R3: one batch element per 128-thread CTA.
// 4096 independent CTAs, 4 resident per SM, drifting freely so one CTA's
// reduction/barrier tail overlaps another's FFMA2 mainloop.
// Thread (g,lane): rows g*4..g*4+3 (rows >=104 are zero pads), cols lane*28..+27.
// G slice (112 floats) in registers as packed f32x2; stage args double-buffered
// in shared; matvec via fma.rn.f32x2; 3-shfl reduce-scatter over 4 lanes.

#define NP 4
#define NC 100
#define NT 104
#define NCOL 112        // padded column count (4 slices of 28)
#define NROW 128        // padded row count (32 groups of 4)
#define THREADS 128
#define NSTEPS 499
#define RESP_LEN 801

typedef unsigned long long u64;

__device__ __forceinline__ u64 pk2(float lo, float hi) {
    u64 r; asm("mov.b64 %0,{%1,%2};" : "=l"(r) : "f"(lo), "f"(hi)); return r;
}
__device__ __forceinline__ void upk2(float& lo, float& hi, u64 v) {
    asm("mov.b64 {%0,%1},%2;" : "=f"(lo), "=f"(hi) : "l"(v));
}
__device__ __forceinline__ void ffma2(u64& d, u64 a, u64 b) {
    asm("fma.rn.f32x2 %0,%1,%2,%3;" : "=l"(d) : "l"(a), "l"(b), "l"(d));
}

__global__ __launch_bounds__(THREADS, 4)
void raman_kernel(const float* __restrict__ x,
                  const float* __restrict__ rr,
                  const float* __restrict__ swl,
                  float* __restrict__ out)
{
    __shared__ float sF[NROW];          // frequencies (rows >= NT zero)
    __shared__ float sA[NROW];          // stage arg buffer A
    __shared__ float sB[NROW];          // stage arg buffer B
    __shared__ float sRR[RESP_LEN];     // raman response

    const int tid  = threadIdx.x;
    const int g    = tid >> 2;          // row group 0..31
    const int lane = tid & 3;           // column lane 0..3
    const int rown = g * 4 + lane;      // row this thread owns after reduction
    const int j0   = lane * 28;
    const bool act = (g < 26);          // groups 26..31 are pure padding rows

    const float* xb = x + blockIdx.x * (2 * NP);

    for (int i = tid; i < RESP_LEN; i += THREADS) sRR[i] = rr[i];

    if (tid < NROW) {
        float f = 0.f, p0 = 0.f;
        if (tid < NT) {
            float lam = (tid < NP) ? xb[tid] : swl[tid - NP];
            f  = __fdiv_rn(299792458.0f, lam);
            p0 = (tid < NP) ? fabsf(xb[NP + tid]) : 0.001f;
        }
        sF[tid] = f;
        sA[tid] = p0;
        sB[tid] = 0.f;
    }
    __syncthreads();

    const float loss = 0.0002f * 0.23025851f;   // only c2 loss term nonzero

    // ---- G slice: rows g*4+k, cols j0..j0+27, packed f32x2 ----
    u64 Gp[56];
    #pragma unroll
    for (int k = 0; k < 4; k++) {
        float fr = act ? sF[g * 4 + k] : 0.f;
        #pragma unroll
        for (int c = 0; c < 14; c++) {
            float gv[2];
            #pragma unroll
            for (int h = 0; h < 2; h++) {
                int j = j0 + 2 * c + h;
                float v = 0.f;
                if (act && j < NT) {
                    float fj   = sF[j];
                    float D    = fj - fr;
                    float fidx = __fdiv_rn(fabsf(D), 50000000000.0f);
                    float fi0  = floorf(fidx);
                    if (fi0 > 799.f) fi0 = 799.f;
                    int   i0   = (int)fi0;
                    float w    = fidx - fi0;
                    float gg   = sRR[i0] * (1.f - w) + sRR[i0 + 1] * w;
                    if (D < 0.f) gg = -gg;
                    float ratio = __fdiv_rn(fr, fj);
                    v = __fdiv_rn(gg * fmaxf(1.f, ratio), 8e-11f);
                }
                gv[h] = v;
            }
            Gp[k * 14 + c] = pk2(gv[0], gv[1]);
        }
    }

    float Pown = sA[rown];              // zero for pad rows

    const double dzd = 50000.0 / 499.0;
    const float  dz       = (float)dzd;
    const float  half_dz  = (float)(0.5 * dzd);
    const float  sixth_dz = (float)(dzd / 6.0);

    const float* pA = sA + j0;
    const float* pB = sB + j0;
    float* wA = sA + rown;
    float* wB = sB + rown;

    auto stagederiv = [&](const float* buf, float argown) -> float {
        u64 a0 = 0, a1 = 0, a2 = 0, a3 = 0;
        const ulonglong2* v = reinterpret_cast<const ulonglong2*>(buf);
        #pragma unroll
        for (int u = 0; u < 7; u++) {
            ulonglong2 p = v[u];
            ffma2(a0, Gp[     2*u], p.x); ffma2(a0, Gp[     2*u + 1], p.y);
            ffma2(a1, Gp[14 + 2*u], p.x); ffma2(a1, Gp[14 + 2*u + 1], p.y);
            ffma2(a2, Gp[28 + 2*u], p.x); ffma2(a2, Gp[28 + 2*u + 1], p.y);
            ffma2(a3, Gp[42 + 2*u], p.x); ffma2(a3, Gp[42 + 2*u + 1], p.y);
        }
        float l0,h0,l1,h1,l2,h2,l3,h3;
        upk2(l0,h0,a0); upk2(l1,h1,a1); upk2(l2,h2,a2); upk2(l3,h3,a3);
        float s0 = l0 + h0, s1 = l1 + h1, s2 = l2 + h2, s3 = l3 + h3;
        // reduce-scatter across the 4 lanes of this group
        bool hi2 = lane & 2;
        float recvA = __shfl_xor_sync(0xffffffffu, hi2 ? s0 : s2, 2);
        float recvB = __shfl_xor_sync(0xffffffffu, hi2 ? s1 : s3, 2);
        float t0 = (hi2 ? s2 : s0) + recvA;
        float t1 = (hi2 ? s3 : s1) + recvB;
        bool hi1 = lane & 1;
        float recvC = __shfl_xor_sync(0xffffffffu, hi1 ? t0 : t1, 1);
        float dot = (hi1 ? t1 : t0) + recvC;
        return (dot - loss) * argown;
    };

    for (int step = 0; step < NSTEPS; step++) {
        float d1 = stagederiv(pA, Pown);
        float a2v = fmaf(half_dz, d1, Pown);
        *wB = a2v;
        __syncthreads();

        float d2 = stagederiv(pB, a2v);
        float a3v = fmaf(half_dz, d2, Pown);
        *wA = a3v;
        __syncthreads();

        float d3 = stagederiv(pA, a3v);
        float a4v = fmaf(dz, d3, Pown);
        *wB = a4v;
        __syncthreads();

        float d4 = stagederiv(pB, a4v);
        Pown = fmaf(sixth_dz, d1 + 2.f * d2 + 2.f * d3 + d4, Pown);
        *wA = Pown;
        __syncthreads();
    }

    if (rown >= NP && rown < NT)
        out[blockIdx.x * NC + (rown - NP)] = Pown;
}

extern "C" void kernel_launch(void* const* d_in, const int* in_sizes, int n_in,
                              void* d_out, int out_size)
{
    const float* x   = (const float*)d_in[0];   // (4096, 8)
    const float* rr  = (const float*)d_in[1];   // (801,)
    const float* swl = (const float*)d_in[2];   // (100,)
    float* out = (float*)d_out;                 // (4096, 100)

    int batch = in_sizes[0] / (2 * NP);
    raman_kernel<<<batch, THREADS>>>(x, rr, swl, out);
}